// round 1
// baseline (speedup 1.0000x reference)
#include <cuda_runtime.h>
#include <math.h>

// ---------------------------------------------------------------------------
// STCNNT cell: LN -> {convK,convQ (s2), convV} -> attention(T=32) -> convO +res
//              -> LN -> convM1+GELU -> convM2 +res
// Shapes: B=4, T=32 (BT=128), C=Cout=32, H=W=64, mixer=128, n_head=8, hd=4
// ---------------------------------------------------------------------------

#define BT 128

// scratch (device globals; no runtime allocation allowed)
__device__ float g_xn [BT * 32 * 64 * 64];    // 64 MB (xn, reused as xn2)
__device__ float g_q  [BT * 32 * 32 * 32];    // 16 MB
__device__ float g_k  [BT * 32 * 32 * 32];    // 16 MB
__device__ float g_v  [BT * 32 * 64 * 64];    // 64 MB
__device__ float g_att[4 * 8 * 32 * 32];      // 128 KB
__device__ float g_y  [BT * 32 * 64 * 64];    // 64 MB
__device__ float g_x1 [BT * 32 * 64 * 64];    // 64 MB
__device__ float g_h  [BT * 128 * 64 * 64];   // 256 MB

__device__ __forceinline__ float gelu_f(float v) {
    float u = 0.7978845608028654f * (v + 0.044715f * v * v * v);
    return 0.5f * v * (1.0f + tanhf(u));
}

// ---------------------------------------------------------------------------
// LayerNorm over (C,H,W) = 131072 elements per (b,t) sample. grid=128, block=256
// ---------------------------------------------------------------------------
__global__ void ln_kernel(const float* __restrict__ x, const float* __restrict__ g,
                          const float* __restrict__ b, float* __restrict__ out) {
    int n = blockIdx.x;
    const float4* x4 = (const float4*)(x + (size_t)n * 131072);
    float s = 0.f, ss = 0.f;
    for (int i = threadIdx.x; i < 32768; i += 256) {
        float4 v = x4[i];
        s  += v.x + v.y + v.z + v.w;
        ss += v.x * v.x + v.y * v.y + v.z * v.z + v.w * v.w;
    }
    __shared__ float rs[8], rss[8];
    #pragma unroll
    for (int o = 16; o > 0; o >>= 1) {
        s  += __shfl_xor_sync(0xffffffffu, s, o);
        ss += __shfl_xor_sync(0xffffffffu, ss, o);
    }
    int w = threadIdx.x >> 5;
    if ((threadIdx.x & 31) == 0) { rs[w] = s; rss[w] = ss; }
    __syncthreads();
    if (threadIdx.x < 32) {
        s  = (threadIdx.x < 8) ? rs[threadIdx.x]  : 0.f;
        ss = (threadIdx.x < 8) ? rss[threadIdx.x] : 0.f;
        #pragma unroll
        for (int o = 4; o > 0; o >>= 1) {
            s  += __shfl_xor_sync(0xffffffffu, s, o);
            ss += __shfl_xor_sync(0xffffffffu, ss, o);
        }
        if (threadIdx.x == 0) { rs[0] = s; rss[0] = ss; }
    }
    __syncthreads();
    float mean = rs[0] * (1.f / 131072.f);
    float var  = rss[0] * (1.f / 131072.f) - mean * mean;
    float rstd = rsqrtf(var + 1e-5f);
    const float4* g4 = (const float4*)g;
    const float4* b4 = (const float4*)b;
    float4* o4 = (float4*)(out + (size_t)n * 131072);
    for (int i = threadIdx.x; i < 32768; i += 256) {
        float4 v = x4[i], gg = g4[i], bb = b4[i], r;
        r.x = (v.x - mean) * rstd * gg.x + bb.x;
        r.y = (v.y - mean) * rstd * gg.y + bb.y;
        r.z = (v.z - mean) * rstd * gg.z + bb.z;
        r.w = (v.w - mean) * rstd * gg.w + bb.w;
        o4[i] = r;
    }
}

// ---------------------------------------------------------------------------
// 3x3 conv, stride 1, pad 1, 64x64 spatial. Block: 256 thr, out tile 64x16,
// 8 couts/block, 4 adjacent x-pixels/thread. Cin looped in chunks of 8.
// grid = (N, Cout/8, 4)
// ---------------------------------------------------------------------------
template<bool HASBIAS, bool GELU, bool RES>
__global__ void conv3x3_s1(const float* __restrict__ in, const float* __restrict__ wt,
                           const float* __restrict__ bias, const float* __restrict__ res,
                           float* __restrict__ out, int Cin, int Cout) {
    __shared__ float s_in[8][18][66];
    __shared__ float s_w[8][8][9];
    int n = blockIdx.x, co0 = blockIdx.y * 8, y0 = blockIdx.z * 16;
    int tid = threadIdx.x;
    int xg = tid & 15, row = tid >> 4;

    float acc[8][4];
    #pragma unroll
    for (int c = 0; c < 8; c++)
        #pragma unroll
        for (int p = 0; p < 4; p++) acc[c][p] = 0.f;

    for (int ci0 = 0; ci0 < Cin; ci0 += 8) {
        __syncthreads();
        for (int i = tid; i < 8 * 18 * 66; i += 256) {
            int ci = i / (18 * 66); int rem = i - ci * (18 * 66);
            int r = rem / 66, c = rem - r * 66;
            int gy = y0 + r - 1, gx = c - 1;
            float v = 0.f;
            if (gy >= 0 && gy < 64 && gx >= 0 && gx < 64)
                v = in[(((size_t)n * Cin + (ci0 + ci)) * 64 + gy) * 64 + gx];
            s_in[ci][r][c] = v;
        }
        for (int i = tid; i < 8 * 8 * 9; i += 256) {
            int co = i / 72; int rem = i - co * 72; int ci = rem / 9; int t = rem - ci * 9;
            s_w[co][ci][t] = wt[((size_t)(co0 + co) * Cin + (ci0 + ci)) * 9 + t];
        }
        __syncthreads();

        for (int ci = 0; ci < 8; ci++) {
            float xv[3][6];
            #pragma unroll
            for (int dy = 0; dy < 3; dy++)
                #pragma unroll
                for (int j = 0; j < 6; j++)
                    xv[dy][j] = s_in[ci][row + dy][4 * xg + j];
            #pragma unroll
            for (int dy = 0; dy < 3; dy++) {
                #pragma unroll
                for (int dx = 0; dx < 3; dx++) {
                    float wv[8];
                    #pragma unroll
                    for (int c = 0; c < 8; c++) wv[c] = s_w[c][ci][dy * 3 + dx];
                    #pragma unroll
                    for (int p = 0; p < 4; p++) {
                        float xx = xv[dy][p + dx];
                        #pragma unroll
                        for (int c = 0; c < 8; c++) acc[c][p] += xx * wv[c];
                    }
                }
            }
        }
    }

    int y = y0 + row;
    #pragma unroll
    for (int c = 0; c < 8; c++) {
        float bv = HASBIAS ? bias[co0 + c] : 0.f;
        float vals[4];
        #pragma unroll
        for (int p = 0; p < 4; p++) {
            float v = acc[c][p] + bv;
            if (GELU) v = gelu_f(v);
            vals[p] = v;
        }
        size_t oidx = (((size_t)n * Cout + co0 + c) * 64 + y) * 64 + 4 * xg;
        if (RES) {
            float4 rv = *(const float4*)(res + oidx);
            vals[0] += rv.x; vals[1] += rv.y; vals[2] += rv.z; vals[3] += rv.w;
        }
        float4 o; o.x = vals[0]; o.y = vals[1]; o.z = vals[2]; o.w = vals[3];
        *(float4*)(out + oidx) = o;
    }
}

// ---------------------------------------------------------------------------
// 3x3 conv, stride 2, pad 1: 64x64 -> 32x32, Cin=Cout=32, no bias.
// Block: 64 thr, out tile 32x8, 8 couts/block, 4 x-pixels/thread.
// grid = (N, 4, 4)
// ---------------------------------------------------------------------------
__global__ void conv3x3_s2(const float* __restrict__ in, const float* __restrict__ wt,
                           float* __restrict__ out) {
    __shared__ float s_in[8][17][66];
    __shared__ float s_w[8][8][9];
    int n = blockIdx.x, co0 = blockIdx.y * 8, y0 = blockIdx.z * 8;
    int tid = threadIdx.x;            // 64 threads
    int xg = tid & 7, row = tid >> 3; // 8 x-groups, 8 rows

    float acc[8][4];
    #pragma unroll
    for (int c = 0; c < 8; c++)
        #pragma unroll
        for (int p = 0; p < 4; p++) acc[c][p] = 0.f;

    for (int ci0 = 0; ci0 < 32; ci0 += 8) {
        __syncthreads();
        for (int i = tid; i < 8 * 17 * 66; i += 64) {
            int ci = i / (17 * 66); int rem = i - ci * (17 * 66);
            int r = rem / 66, c = rem - r * 66;
            int gy = 2 * y0 - 1 + r, gx = c - 1;
            float v = 0.f;
            if (gy >= 0 && gy < 64 && gx >= 0 && gx < 64)
                v = in[(((size_t)n * 32 + (ci0 + ci)) * 64 + gy) * 64 + gx];
            s_in[ci][r][c] = v;
        }
        for (int i = tid; i < 576; i += 64) {
            int co = i / 72; int rem = i - co * 72; int ci = rem / 9; int t = rem - ci * 9;
            s_w[co][ci][t] = wt[((size_t)(co0 + co) * 32 + (ci0 + ci)) * 9 + t];
        }
        __syncthreads();

        for (int ci = 0; ci < 8; ci++) {
            float xv[3][9];
            #pragma unroll
            for (int dy = 0; dy < 3; dy++)
                #pragma unroll
                for (int j = 0; j < 9; j++)
                    xv[dy][j] = s_in[ci][2 * row + dy][8 * xg + j];
            #pragma unroll
            for (int dy = 0; dy < 3; dy++) {
                #pragma unroll
                for (int dx = 0; dx < 3; dx++) {
                    float wv[8];
                    #pragma unroll
                    for (int c = 0; c < 8; c++) wv[c] = s_w[c][ci][dy * 3 + dx];
                    #pragma unroll
                    for (int p = 0; p < 4; p++) {
                        float xx = xv[dy][2 * p + dx];
                        #pragma unroll
                        for (int c = 0; c < 8; c++) acc[c][p] += xx * wv[c];
                    }
                }
            }
        }
    }

    int y = y0 + row;
    #pragma unroll
    for (int c = 0; c < 8; c++) {
        size_t oidx = (((size_t)n * 32 + co0 + c) * 32 + y) * 32 + 4 * xg;
        float4 o; o.x = acc[c][0]; o.y = acc[c][1]; o.z = acc[c][2]; o.w = acc[c][3];
        *(float4*)(out + oidx) = o;
    }
}

// ---------------------------------------------------------------------------
// att[b,h,t,s] = softmax_s( q[b,h,t,:] . k[b,h,s,:] / 64 ), d_k = 4096
// q,k layout: [BT, 32, 32, 32]; (b,t,h) slice contiguous 4096 floats.
// grid = 1024 (b*8*32 + ...), block = 256 (8 warps; warp computes 4 s-dots)
// ---------------------------------------------------------------------------
__global__ void qk_softmax_kernel(const float* __restrict__ q, const float* __restrict__ k,
                                  float* __restrict__ att) {
    int bx = blockIdx.x;
    int t = bx & 31, bh = bx >> 5, h = bh & 7, b = bh >> 3;
    int lane = threadIdx.x & 31, w = threadIdx.x >> 5;
    const float4* q4 = (const float4*)(q + ((size_t)(b * 32 + t) * 32 + h * 4) * 1024);
    __shared__ float sS[32];
    #pragma unroll
    for (int si = 0; si < 4; si++) {
        int s = w * 4 + si;
        const float4* k4 = (const float4*)(k + ((size_t)(b * 32 + s) * 32 + h * 4) * 1024);
        float acc = 0.f;
        for (int d = lane; d < 1024; d += 32) {
            float4 qv = q4[d], kv = k4[d];
            acc += qv.x * kv.x + qv.y * kv.y + qv.z * kv.z + qv.w * kv.w;
        }
        #pragma unroll
        for (int o = 16; o > 0; o >>= 1) acc += __shfl_xor_sync(0xffffffffu, acc, o);
        if (lane == 0) sS[s] = acc * (1.f / 64.f);
    }
    __syncthreads();
    if (threadIdx.x < 32) {
        float v = sS[threadIdx.x];
        float m = v;
        #pragma unroll
        for (int o = 16; o > 0; o >>= 1) m = fmaxf(m, __shfl_xor_sync(0xffffffffu, m, o));
        float e = expf(v - m);
        float sum = e;
        #pragma unroll
        for (int o = 16; o > 0; o >>= 1) sum += __shfl_xor_sync(0xffffffffu, sum, o);
        att[(size_t)bx * 32 + threadIdx.x] = e / sum;
    }
}

// ---------------------------------------------------------------------------
// y[b,h,t,d] = sum_s att[b,h,t,s] * v[b,h,s,d], d_v = 16384.
// grid = (32, 64), block = 256; thread owns one d, 32 t-accumulators.
// ---------------------------------------------------------------------------
__global__ void av_kernel(const float* __restrict__ att, const float* __restrict__ v,
                          float* __restrict__ y) {
    int bh = blockIdx.x, b = bh >> 3, h = bh & 7;
    int d = blockIdx.y * 256 + threadIdx.x;
    __shared__ __align__(16) float sA[32][36];  // sA[s][t] (transposed)
    for (int i = threadIdx.x; i < 1024; i += 256) {
        int t = i >> 5, s = i & 31;
        sA[s][t] = att[((size_t)bh * 32 + t) * 32 + s];
    }
    __syncthreads();
    const float* vb = v + (size_t)b * 32 * 131072 + (size_t)h * 16384 + d;
    float acc[32];
    #pragma unroll
    for (int t = 0; t < 32; t++) acc[t] = 0.f;
    #pragma unroll 4
    for (int s = 0; s < 32; s++) {
        float vv = vb[(size_t)s * 131072];
        const float4* a4 = (const float4*)&sA[s][0];
        #pragma unroll
        for (int t4 = 0; t4 < 8; t4++) {
            float4 a = a4[t4];
            acc[4 * t4 + 0] += a.x * vv;
            acc[4 * t4 + 1] += a.y * vv;
            acc[4 * t4 + 2] += a.z * vv;
            acc[4 * t4 + 3] += a.w * vv;
        }
    }
    float* yb = y + (size_t)b * 32 * 131072 + (size_t)h * 16384 + d;
    #pragma unroll
    for (int t = 0; t < 32; t++) yb[(size_t)t * 131072] = acc[t];
}

// ---------------------------------------------------------------------------
extern "C" void kernel_launch(void* const* d_in, const int* in_sizes, int n_in,
                              void* d_out, int out_size) {
    const float* x   = (const float*)d_in[0];
    const float* n1g = (const float*)d_in[1];
    const float* n1b = (const float*)d_in[2];
    const float* n2g = (const float*)d_in[3];
    const float* n2b = (const float*)d_in[4];
    const float* Wk  = (const float*)d_in[5];
    const float* Wq  = (const float*)d_in[6];
    const float* Wv  = (const float*)d_in[7];
    const float* Wo  = (const float*)d_in[8];
    const float* bo  = (const float*)d_in[9];
    const float* Wm1 = (const float*)d_in[10];
    const float* bm1 = (const float*)d_in[11];
    const float* Wm2 = (const float*)d_in[12];
    const float* bm2 = (const float*)d_in[13];
    float* out = (float*)d_out;

    float *xn, *q, *k, *v, *att, *y, *x1, *h;
    cudaGetSymbolAddress((void**)&xn,  g_xn);
    cudaGetSymbolAddress((void**)&q,   g_q);
    cudaGetSymbolAddress((void**)&k,   g_k);
    cudaGetSymbolAddress((void**)&v,   g_v);
    cudaGetSymbolAddress((void**)&att, g_att);
    cudaGetSymbolAddress((void**)&y,   g_y);
    cudaGetSymbolAddress((void**)&x1,  g_x1);
    cudaGetSymbolAddress((void**)&h,   g_h);

    // 1. LN1
    ln_kernel<<<128, 256>>>(x, n1g, n1b, xn);
    // 2-4. k, q (stride-2), v (stride-1) convs
    conv3x3_s2<<<dim3(128, 4, 4), 64>>>(xn, Wk, k);
    conv3x3_s2<<<dim3(128, 4, 4), 64>>>(xn, Wq, q);
    conv3x3_s1<false, false, false><<<dim3(128, 4, 4), 256>>>(xn, Wv, nullptr, nullptr, v, 32, 32);
    // 5. scores + softmax
    qk_softmax_kernel<<<1024, 256>>>(q, k, att);
    // 6. att @ v
    av_kernel<<<dim3(32, 64), 256>>>(att, v, y);
    // 7. output projection conv + bias + residual(x)
    conv3x3_s1<true, false, true><<<dim3(128, 4, 4), 256>>>(y, Wo, bo, x, x1, 32, 32);
    // 8. LN2
    ln_kernel<<<128, 256>>>(x1, n2g, n2b, xn);
    // 9. mixer conv1 + bias + GELU (32 -> 128)
    conv3x3_s1<true, true, false><<<dim3(128, 16, 4), 256>>>(xn, Wm1, bm1, nullptr, h, 32, 128);
    // 10. mixer conv2 + bias + residual(x1) (128 -> 32) -> final output
    conv3x3_s1<true, false, true><<<dim3(128, 4, 4), 256>>>(h, Wm2, bm2, x1, out, 128, 32);
}